// round 8
// baseline (speedup 1.0000x reference)
#include <cuda_runtime.h>
#include <cuda_fp16.h>
#include <math.h>

#define HH 256
#define WW 256
#define HW 65536
#define NB 8
#define NSLICE 24      // NB * 3 kept channels
#define NPIX (NB*HW)   // 524288
#define RPB 2          // rows per block in k_main
#define NMAIN (NSLICE * (HH / RPB))   // 3072 blocks
#define DBIG 1024      // "no bit found in row" sentinel distance

// -------- device scratch (no allocations allowed) --------
// row-packed mask bits: [plane(2)][slice(24)][row(256)][word(8)]
__device__ unsigned g_row[2 * NSLICE * HH * 8];
__device__ __half2  g_err2[NSLICE * HW / 2];     // (p - t)^2 per kept channel, fp16
__device__ int      g_cnt[2 * NSLICE];           // [0..23] p-counts, [24..47] t-counts
__device__ double   g_acc;
__device__ int      g_done;

// 16-bit -> even bit positions of 32-bit
__device__ __forceinline__ unsigned morton16(unsigned v) {
    v = (v | (v << 8)) & 0x00FF00FFu;
    v = (v | (v << 4)) & 0x0F0F0F0Fu;
    v = (v | (v << 2)) & 0x33333333u;
    v = (v | (v << 1)) & 0x55555555u;
    return v;
}

// per-pixel softmax(4) + argmax(4) -> squared errors of ch 1..3 + 6 mask bits
__device__ __forceinline__ void pixel_work(float s0, float s1, float s2, float s3,
                                           float t0, float t1, float t2, float t3,
                                           float& e1o, float& e2o, float& e3o,
                                           unsigned& mk) {
    float m  = fmaxf(fmaxf(s0, s1), fmaxf(s2, s3));
    float e0 = __expf(s0 - m), e1 = __expf(s1 - m), e2 = __expf(s2 - m), e3 = __expf(s3 - m);
    float inv = 1.0f / (e0 + e1 + e2 + e3);
    float p1 = e1 * inv, p2 = e2 * inv, p3 = e3 * inv;

    int lab = 0; float best = t0;            // first-index-wins (matches jnp.argmax)
    if (t1 > best) { best = t1; lab = 1; }
    if (t2 > best) { best = t2; lab = 2; }
    if (t3 > best) { best = t3; lab = 3; }

    float g1 = (lab == 1) ? 1.0f : 0.0f;
    float g2 = (lab == 2) ? 1.0f : 0.0f;
    float g3 = (lab == 3) ? 1.0f : 0.0f;
    e1o = (p1 - g1) * (p1 - g1);
    e2o = (p2 - g2) * (p2 - g2);
    e3o = (p3 - g3) * (p3 - g3);

    mk = 0;
    if (p1 > 0.5f) mk |= 1u;
    if (p2 > 0.5f) mk |= 2u;
    if (p3 > 0.5f) mk |= 4u;
    mk |= ((unsigned)g1 << 3) | ((unsigned)g2 << 4) | ((unsigned)g3 << 5);
}

// -------- kernel 1: softmax + argmax + err + ballot row-packing + counts --------
// 2 px/thread (float2). One warp = 64 consecutive columns of one row.
__global__ void __launch_bounds__(256) k_prep(const float2* __restrict__ S2,
                                              const float2* __restrict__ T2) {
    if (blockIdx.x == 0) {                      // accumulators consumed only by LATER kernels
        if (threadIdx.x < 2 * NSLICE) g_cnt[threadIdx.x] = 0;
        if (threadIdx.x == 2 * NSLICE) { g_acc = 0.0; g_done = 0; }
    }

    int q    = blockIdx.x * 256 + threadIdx.x; // pixel-pair index
    int b    = q >> 15;                        // 32768 pairs per image (block never straddles b)
    int pq   = q & 32767;
    int lane = threadIdx.x & 31;

    const float2* s = S2 + (size_t)b * 4 * 32768 + pq;
    float2 s0 = s[0], s1 = s[32768], s2 = s[2 * 32768], s3 = s[3 * 32768];
    const float2* t = T2 + (size_t)b * 4 * 32768 + pq;
    float2 t0 = t[0], t1 = t[32768], t2 = t[2 * 32768], t3 = t[3 * 32768];

    float a1, a2, a3, b1, b2, b3;
    unsigned m0, m1;
    pixel_work(s0.x, s1.x, s2.x, s3.x, t0.x, t1.x, t2.x, t3.x, a1, a2, a3, m0);
    pixel_work(s0.y, s1.y, s2.y, s3.y, t0.y, t1.y, t2.y, t3.y, b1, b2, b3, m1);

    int base = (b * 3) * 32768 + pq;
    g_err2[base]             = __floats2half2_rn(a1, b1);
    g_err2[base + 32768]     = __floats2half2_rn(a2, b2);
    g_err2[base + 2 * 32768] = __floats2half2_rn(a3, b3);

    // ballots per bit-plane (px0 and px1 separately)
    unsigned B00 = __ballot_sync(0xffffffffu, (m0 >> 0) & 1), B01 = __ballot_sync(0xffffffffu, (m1 >> 0) & 1);
    unsigned B10 = __ballot_sync(0xffffffffu, (m0 >> 1) & 1), B11 = __ballot_sync(0xffffffffu, (m1 >> 1) & 1);
    unsigned B20 = __ballot_sync(0xffffffffu, (m0 >> 2) & 1), B21 = __ballot_sync(0xffffffffu, (m1 >> 2) & 1);
    unsigned B30 = __ballot_sync(0xffffffffu, (m0 >> 3) & 1), B31 = __ballot_sync(0xffffffffu, (m1 >> 3) & 1);
    unsigned B40 = __ballot_sync(0xffffffffu, (m0 >> 4) & 1), B41 = __ballot_sync(0xffffffffu, (m1 >> 4) & 1);
    unsigned B50 = __ballot_sync(0xffffffffu, (m0 >> 5) & 1), B51 = __ballot_sync(0xffffffffu, (m1 >> 5) & 1);

    // per-slice counts (for valid = any() && !all()): popc of ballots, once per warp
    __shared__ int scnt[6];
    if (threadIdx.x < 6) scnt[threadIdx.x] = 0;
    __syncthreads();
    if (lane == 0) {
        atomicAdd(&scnt[0], __popc(B00) + __popc(B01));
        atomicAdd(&scnt[1], __popc(B10) + __popc(B11));
        atomicAdd(&scnt[2], __popc(B20) + __popc(B21));
        atomicAdd(&scnt[3], __popc(B30) + __popc(B31));
        atomicAdd(&scnt[4], __popc(B40) + __popc(B41));
        atomicAdd(&scnt[5], __popc(B50) + __popc(B51));
    }

    // lanes 0..11 each store one packed word: plane = lane>>1, hi-half = lane&1
    int beta = lane >> 1;
    int hi   = lane & 1;
    unsigned sel0 = (beta == 0) ? B00 : (beta == 1) ? B10 : (beta == 2) ? B20
                  : (beta == 3) ? B30 : (beta == 4) ? B40 : B50;
    unsigned sel1 = (beta == 0) ? B01 : (beta == 1) ? B11 : (beta == 2) ? B21
                  : (beta == 3) ? B31 : (beta == 4) ? B41 : B51;
    unsigned p0 = hi ? (sel0 >> 16) : (sel0 & 0xFFFFu);
    unsigned p1 = hi ? (sel1 >> 16) : (sel1 & 0xFFFFu);
    unsigned word = morton16(p0) | (morton16(p1) << 1);

    if (lane < 12) {
        int row   = pq >> 7;                     // 128 pairs per row
        int wbase = (((pq & 127) >> 5) << 1);    // warp covers words wbase, wbase+1
        int P  = (beta >= 3) ? 1 : 0;
        int cc = beta - 3 * P;
        int sl = b * 3 + cc;
        g_row[((P * NSLICE + sl) * HH + row) * 8 + wbase + hi] = word;
    }

    __syncthreads();
    if (threadIdx.x < 3)      atomicAdd(&g_cnt[b * 3 + threadIdx.x], scnt[threadIdx.x]);
    else if (threadIdx.x < 6) atomicAdd(&g_cnt[NSLICE + b * 3 + threadIdx.x - 3], scnt[threadIdx.x]);
}

// nearest set bit (after XOR with x) in a 256-bit packed row, distance from column j.
// Returns DBIG if none within dcmax. Exact for distances <= dcmax.
__device__ __forceinline__ int probe(const unsigned* __restrict__ rw, unsigned x,
                                     int j, int dcmax) {
    int w = j >> 5, o = j & 31;
    unsigned c = rw[w] ^ x;
    int d = DBIG;
    unsigned hbits = c & (0xFFFFFFFFu << o);
    if (hbits) d = (__ffs(hbits) - 1) - o;
    unsigned lbits = c & (0xFFFFFFFFu >> (31 - o));
    if (lbits) d = min(d, o - (31 - __clz(lbits)));
    // word-walk right
    for (int k = w + 1; k < 8; k++) {
        int mind = k * 32 - j;
        if (mind >= d || mind > dcmax) break;
        unsigned cc = rw[k] ^ x;
        if (cc) { d = min(d, mind + __ffs(cc) - 1); break; }
    }
    // word-walk left
    for (int k = w - 1; k >= 0; k--) {
        int mind = j - (k * 32 + 31);
        if (mind >= d || mind > dcmax) break;
        unsigned cc = rw[k] ^ x;
        if (cc) { d = min(d, j - (k * 32 + 31 - __clz(cc))); break; }
    }
    return d;
}

// squared distance to nearest pixel whose plane-bit differs from own bit (exact).
__device__ __forceinline__ int edt2d(const unsigned* __restrict__ plane,
                                     int r, int j, unsigned x) {
    int dc = probe(plane + r * 8, x, j, 256);
    int best = (dc < DBIG) ? dc * dc : (1 << 22);
    for (int dr = 1; dr < HH && dr * dr < best; dr++) {
        int rem = best - dr * dr;
        int dcmax = __float2int_rz(__fsqrt_rn((float)rem)) + 1;  // overshoot-safe bound
        int up = r - dr, dn = r + dr;
        if (up >= 0) {
            int d = probe(plane + up * 8, x, j, dcmax);
            if (d < DBIG) best = min(best, dr * dr + d * d);
        }
        if (dn < HH) {
            int d = probe(plane + dn * 8, x, j, dcmax);
            if (d < DBIG) best = min(best, dr * dr + d * d);
        }
    }
    return best;
}

// -------- kernel 2: 2D nearest-differing-bit EDT + loss + finalize --------
// block = (slice, 2-row band); grid = 24*128 = 3072
__global__ void __launch_bounds__(256) k_main(float* __restrict__ out) {
    int s    = blockIdx.x >> 7;    // slice 0..23
    int band = blockIdx.x & 127;   // 2-row band
    int j    = threadIdx.x;        // column

    const unsigned* rp = g_row + (size_t)(0 * NSLICE + s) * HH * 8;
    const unsigned* rt = g_row + (size_t)(1 * NSLICE + s) * HH * 8;

    int cp = g_cnt[s], ct = g_cnt[NSLICE + s];
    bool vp = (cp > 0 && cp < HW);
    bool vt = (ct > 0 && ct < HW);

    const __half* erow = ((const __half*)g_err2) + (size_t)s * HW + (size_t)band * RPB * WW + j;

    float acc = 0.0f;
    #pragma unroll
    for (int rr = 0; rr < RPB; rr++) {
        int r = band * RPB + rr;
        unsigned wP = rp[r * 8 + (j >> 5)];
        unsigned wT = rt[r * 8 + (j >> 5)];
        unsigned xP = ((wP >> (j & 31)) & 1u) ? 0xFFFFFFFFu : 0u;
        unsigned xT = ((wT >> (j & 31)) & 1u) ? 0xFFFFFFFFu : 0u;
        int dp2 = vp ? edt2d(rp, r, j, xP) : 0;
        int dt2 = vt ? edt2d(rt, r, j, xT) : 0;
        float err = __half2float(erow[rr * WW]);
        acc += err * (float)(dp2 + dt2);
    }

    // block reduction -> double atomic (once per block)
    #pragma unroll
    for (int o = 16; o; o >>= 1) acc += __shfl_down_sync(0xffffffffu, acc, o);
    __shared__ float wsum[8];
    if ((threadIdx.x & 31) == 0) wsum[threadIdx.x >> 5] = acc;
    __syncthreads();
    if (threadIdx.x == 0) {
        float ssum = 0.0f;
        #pragma unroll
        for (int w = 0; w < 8; w++) ssum += wsum[w];
        atomicAdd(&g_acc, (double)ssum);
        __threadfence();
        int ticket = atomicAdd(&g_done, 1);
        if (ticket == NMAIN - 1) {             // last block finalizes
            double total = atomicAdd(&g_acc, 0.0);
            double mean  = total / (double)(NSLICE * HW);
            out[0] = (float)log(mean + 1.0);
        }
    }
}

extern "C" void kernel_launch(void* const* d_in, const int* in_sizes, int n_in,
                              void* d_out, int out_size) {
    const float2* S = (const float2*)d_in[0];   // preds_S (8,4,256,256)
    const float2* T = (const float2*)d_in[1];   // preds_T (8,4,256,256)
    (void)in_sizes; (void)n_in; (void)out_size; // target (d_in[2]) unused by reference

    k_prep<<<NPIX / 2 / 256, 256>>>(S, T);
    k_main<<<NMAIN, 256>>>((float*)d_out);
}

// round 9
// speedup vs baseline: 1.8056x; 1.8056x over previous
#include <cuda_runtime.h>
#include <cuda_fp16.h>
#include <math.h>

#define HH 256
#define WW 256
#define HW 65536
#define NB 8
#define NSLICE 24      // NB * 3 kept channels
#define NPIX (NB*HW)   // 524288
#define CAP 512        // INF = H + W in reference
#define BIG (1<<20)
#define RPB 4          // rows per block in k_main
#define NMAIN (NSLICE * (HH / RPB))   // 1536 blocks
#define WIN 5          // unconditional search window

// -------- device scratch (no allocations allowed) --------
// row-packed mask bits: [plane(2)][slice(24)][row(256)][word(8)] (bit = col within word)
__device__ unsigned g_row[2 * NSLICE * HH * 8];
// column-packed bits: [plane(2)][slice(24)][roww(8)][col(256)] (bit i = row roww*32+i)
__device__ unsigned g_bits[2 * NSLICE * 8 * WW];
__device__ __half2  g_err2[NSLICE * HW / 2];     // (p - t)^2 per kept channel, fp16
__device__ int      g_cnt[2 * NSLICE];           // [0..23] p-counts, [24..47] t-counts
__device__ double   g_acc;
__device__ int      g_done;

// 16-bit -> even bit positions of 32-bit
__device__ __forceinline__ unsigned morton16(unsigned v) {
    v = (v | (v << 8)) & 0x00FF00FFu;
    v = (v | (v << 4)) & 0x0F0F0F0Fu;
    v = (v | (v << 2)) & 0x33333333u;
    v = (v | (v << 1)) & 0x55555555u;
    return v;
}

// per-pixel softmax(4) + argmax(4) -> squared errors of ch 1..3 + 6 mask bits
__device__ __forceinline__ void pixel_work(float s0, float s1, float s2, float s3,
                                           float t0, float t1, float t2, float t3,
                                           float& e1o, float& e2o, float& e3o,
                                           unsigned& mk) {
    float m  = fmaxf(fmaxf(s0, s1), fmaxf(s2, s3));
    float e0 = __expf(s0 - m), e1 = __expf(s1 - m), e2 = __expf(s2 - m), e3 = __expf(s3 - m);
    float inv = 1.0f / (e0 + e1 + e2 + e3);
    float p1 = e1 * inv, p2 = e2 * inv, p3 = e3 * inv;

    int lab = 0; float best = t0;            // first-index-wins (matches jnp.argmax)
    if (t1 > best) { best = t1; lab = 1; }
    if (t2 > best) { best = t2; lab = 2; }
    if (t3 > best) { best = t3; lab = 3; }

    float g1 = (lab == 1) ? 1.0f : 0.0f;
    float g2 = (lab == 2) ? 1.0f : 0.0f;
    float g3 = (lab == 3) ? 1.0f : 0.0f;
    e1o = (p1 - g1) * (p1 - g1);
    e2o = (p2 - g2) * (p2 - g2);
    e3o = (p3 - g3) * (p3 - g3);

    mk = 0;
    if (p1 > 0.5f) mk |= 1u;
    if (p2 > 0.5f) mk |= 2u;
    if (p3 > 0.5f) mk |= 4u;
    mk |= ((unsigned)g1 << 3) | ((unsigned)g2 << 4) | ((unsigned)g3 << 5);
}

// -------- kernel 1: softmax + argmax + err + ballot row-packing + counts --------
// 2 px/thread (float2). One warp = 64 consecutive columns of one row.
__global__ void __launch_bounds__(256) k_prep(const float2* __restrict__ S2,
                                              const float2* __restrict__ T2) {
    if (blockIdx.x == 0) {                      // accumulators consumed only by LATER kernels
        if (threadIdx.x < 2 * NSLICE) g_cnt[threadIdx.x] = 0;
        if (threadIdx.x == 2 * NSLICE) { g_acc = 0.0; g_done = 0; }
    }

    int q    = blockIdx.x * 256 + threadIdx.x; // pixel-pair index
    int b    = q >> 15;                        // 32768 pairs per image (block never straddles b)
    int pq   = q & 32767;
    int lane = threadIdx.x & 31;

    const float2* s = S2 + (size_t)b * 4 * 32768 + pq;
    float2 s0 = s[0], s1 = s[32768], s2 = s[2 * 32768], s3 = s[3 * 32768];
    const float2* t = T2 + (size_t)b * 4 * 32768 + pq;
    float2 t0 = t[0], t1 = t[32768], t2 = t[2 * 32768], t3 = t[3 * 32768];

    float a1, a2, a3, b1, b2, b3;
    unsigned m0, m1;
    pixel_work(s0.x, s1.x, s2.x, s3.x, t0.x, t1.x, t2.x, t3.x, a1, a2, a3, m0);
    pixel_work(s0.y, s1.y, s2.y, s3.y, t0.y, t1.y, t2.y, t3.y, b1, b2, b3, m1);

    int base = (b * 3) * 32768 + pq;
    g_err2[base]             = __floats2half2_rn(a1, b1);
    g_err2[base + 32768]     = __floats2half2_rn(a2, b2);
    g_err2[base + 2 * 32768] = __floats2half2_rn(a3, b3);

    // ballots per bit-plane (px0 and px1 separately)
    unsigned B00 = __ballot_sync(0xffffffffu, (m0 >> 0) & 1), B01 = __ballot_sync(0xffffffffu, (m1 >> 0) & 1);
    unsigned B10 = __ballot_sync(0xffffffffu, (m0 >> 1) & 1), B11 = __ballot_sync(0xffffffffu, (m1 >> 1) & 1);
    unsigned B20 = __ballot_sync(0xffffffffu, (m0 >> 2) & 1), B21 = __ballot_sync(0xffffffffu, (m1 >> 2) & 1);
    unsigned B30 = __ballot_sync(0xffffffffu, (m0 >> 3) & 1), B31 = __ballot_sync(0xffffffffu, (m1 >> 3) & 1);
    unsigned B40 = __ballot_sync(0xffffffffu, (m0 >> 4) & 1), B41 = __ballot_sync(0xffffffffu, (m1 >> 4) & 1);
    unsigned B50 = __ballot_sync(0xffffffffu, (m0 >> 5) & 1), B51 = __ballot_sync(0xffffffffu, (m1 >> 5) & 1);

    // per-slice counts (for valid = any() && !all()): popc of ballots, once per warp
    __shared__ int scnt[6];
    if (threadIdx.x < 6) scnt[threadIdx.x] = 0;
    __syncthreads();
    if (lane == 0) {
        atomicAdd(&scnt[0], __popc(B00) + __popc(B01));
        atomicAdd(&scnt[1], __popc(B10) + __popc(B11));
        atomicAdd(&scnt[2], __popc(B20) + __popc(B21));
        atomicAdd(&scnt[3], __popc(B30) + __popc(B31));
        atomicAdd(&scnt[4], __popc(B40) + __popc(B41));
        atomicAdd(&scnt[5], __popc(B50) + __popc(B51));
    }

    // lanes 0..11 each store one packed word: plane = lane>>1, hi-half = lane&1
    int beta = lane >> 1;
    int hi   = lane & 1;
    unsigned sel0 = (beta == 0) ? B00 : (beta == 1) ? B10 : (beta == 2) ? B20
                  : (beta == 3) ? B30 : (beta == 4) ? B40 : B50;
    unsigned sel1 = (beta == 0) ? B01 : (beta == 1) ? B11 : (beta == 2) ? B21
                  : (beta == 3) ? B31 : (beta == 4) ? B41 : B51;
    unsigned p0 = hi ? (sel0 >> 16) : (sel0 & 0xFFFFu);
    unsigned p1 = hi ? (sel1 >> 16) : (sel1 & 0xFFFFu);
    unsigned word = morton16(p0) | (morton16(p1) << 1);

    if (lane < 12) {
        int row   = pq >> 7;                     // 128 pairs per row
        int wbase = (((pq & 127) >> 5) << 1);    // warp covers words wbase, wbase+1
        int P  = (beta >= 3) ? 1 : 0;
        int cc = beta - 3 * P;
        int sl = b * 3 + cc;
        g_row[((P * NSLICE + sl) * HH + row) * 8 + wbase + hi] = word;
    }

    __syncthreads();
    if (threadIdx.x < 3)      atomicAdd(&g_cnt[b * 3 + threadIdx.x], scnt[threadIdx.x]);
    else if (threadIdx.x < 6) atomicAdd(&g_cnt[NSLICE + b * 3 + threadIdx.x - 3], scnt[threadIdx.x]);
}

// -------- kernel 2: 32x32 bit-matrix transpose, row-packed -> column-packed --------
// one warp per tile; tiles = 2 planes * 24 slices * 8 row-words * 8 col-words = 3072
__global__ void __launch_bounds__(256) k_trans() {
    int warpid = (blockIdx.x * 256 + threadIdx.x) >> 5;   // 0..3071
    int lane   = threadIdx.x & 31;
    int C  = warpid & 7;          // column-word of source (32 columns)
    int W  = (warpid >> 3) & 7;   // row-word of dest (32 rows)
    int ps = warpid >> 6;         // plane*NSLICE + slice, 0..47

    unsigned in = g_row[((size_t)ps * HH + 32 * W + lane) * 8 + C];

    unsigned out = 0;
    #pragma unroll
    for (int k = 0; k < 32; k++) {
        unsigned bal = __ballot_sync(0xffffffffu, (in >> k) & 1u);
        if (lane == k) out = bal;
    }
    g_bits[(size_t)ps * 8 * WW + W * WW + 32 * C + lane] = out;
}

// exact search: unconditional ±WIN window (independent LDS, clamped indices are
// over-estimates of valid candidates -> still exact), then rare break-loop tail
__device__ __forceinline__ int edt_search(const int* __restrict__ G, int j) {
    int best = G[j];
    #pragma unroll
    for (int d = 1; d <= WIN; d++) {
        int dd = d * d;
        int a = G[max(j - d, 0)] + dd;
        int b = G[min(j + d, WW - 1)] + dd;
        best = min(best, min(a, b));
    }
    if ((WIN + 1) * (WIN + 1) < best) {
        for (int d = WIN + 1; d < WW; d++) {
            int dd = d * d;
            if (dd >= best) break;
            int jm = j - d, jp = j + d;
            if (jm >= 0) best = min(best, G[jm] + dd);
            if (jp < WW) best = min(best, G[jp] + dd);
        }
    }
    return best;
}

// on-demand out-of-word fallbacks for one plane/column (early-break; usually 1 iter)
__device__ __forceinline__ void fallbacks(const unsigned* __restrict__ P, int j, int w0,
                                          int& fb0, int& fb1, int& la0, int& la1) {
    fb0 = BIG; fb1 = BIG;
    for (int w = w0 + 1; w < 8 && (fb0 == BIG || fb1 == BIG); w++) {
        unsigned ww = P[w * WW + j];
        if (fb0 == BIG && ~ww) fb0 = w * 32 + __ffs(~ww) - 1;
        if (fb1 == BIG &&  ww) fb1 = w * 32 + __ffs(ww) - 1;
    }
    la0 = -BIG; la1 = -BIG;
    for (int w = w0 - 1; w >= 0 && (la0 == -BIG || la1 == -BIG); w--) {
        unsigned ww = P[w * WW + j];
        if (la0 == -BIG && ~ww) la0 = w * 32 + 31 - __clz(~ww);
        if (la1 == -BIG &&  ww) la1 = w * 32 + 31 - __clz(ww);
    }
}

// per-row vertical distances from register word + precomputed fallbacks
__device__ __forceinline__ void vrow(unsigned cur, int br, int R,
                                     int fb0, int fb1, int la0, int la1,
                                     int& d0, int& d1) {
    unsigned hi = 0xFFFFFFFFu << br;
    unsigned lo = 0xFFFFFFFFu >> (31 - br);
    unsigned nc = ~cur;

    unsigned x0 = nc & hi;
    int dn0 = x0 ? (__ffs(x0) - 1 - br) : (fb0 - R);
    unsigned y0 = nc & lo;
    int up0 = y0 ? (br - (31 - __clz(y0))) : (R - la0);
    d0 = min(min(dn0, up0), CAP);

    unsigned x1 = cur & hi;
    int dn1 = x1 ? (__ffs(x1) - 1 - br) : (fb1 - R);
    unsigned y1 = cur & lo;
    int up1 = y1 ? (br - (31 - __clz(y1))) : (R - la1);
    d1 = min(min(dn1, up1), CAP);
}

// -------- kernel 3: fused vertical+horizontal EDT + loss + finalize --------
// block = (slice, 4-row band); grid = 24*64 = 1536
__global__ void __launch_bounds__(256) k_main(float* __restrict__ out) {
    int s    = blockIdx.x >> 6;    // slice 0..23
    int band = blockIdx.x & 63;    // 4-row band 0..63
    int j    = threadIdx.x;        // column
    int w0   = band >> 3;          // word holding all 4 rows
    int bb   = (band & 7) * 4;     // bit base within word

    const unsigned* Pp = g_bits + (size_t)(0 * NSLICE + s) * 8 * WW;
    const unsigned* Pt = g_bits + (size_t)(1 * NSLICE + s) * 8 * WW;

    unsigned curp = Pp[w0 * WW + j];
    unsigned curt = Pt[w0 * WW + j];
    int fb0p, fb1p, la0p, la1p, fb0t, fb1t, la0t, la1t;
    fallbacks(Pp, j, w0, fb0p, fb1p, la0p, la1p);
    fallbacks(Pt, j, w0, fb0t, fb1t, la0t, la1t);

    __shared__ int G[RPB][4][WW];
    #pragma unroll
    for (int r = 0; r < RPB; r++) {
        int br = bb + r;
        int R  = band * RPB + r;
        int d0, d1;
        vrow(curp, br, R, fb0p, fb1p, la0p, la1p, d0, d1);
        G[r][0][j] = d0 * d0;
        G[r][1][j] = d1 * d1;
        vrow(curt, br, R, fb0t, fb1t, la0t, la1t, d0, d1);
        G[r][2][j] = d0 * d0;
        G[r][3][j] = d1 * d1;
    }
    __syncthreads();               // ONE barrier per block

    int cp = g_cnt[s], ct = g_cnt[NSLICE + s];
    float vp = (cp > 0 && cp < HW) ? 1.0f : 0.0f;
    float vt = (ct > 0 && ct < HW) ? 1.0f : 0.0f;

    const __half* erow = ((const __half*)g_err2) + (size_t)s * HW + (size_t)band * RPB * WW + j;

    float acc = 0.0f;
    #pragma unroll
    for (int r = 0; r < RPB; r++) {
        int br = bb + r;
        int p_true = (curp >> br) & 1;
        int t_true = (curt >> br) & 1;
        int dp = edt_search(&G[r][p_true ? 0 : 1][0], j);
        int dt = edt_search(&G[r][t_true ? 2 : 3][0], j);
        float err = __half2float(erow[r * WW]);
        acc += err * ((float)dp * vp + (float)dt * vt);
    }

    // block reduction -> double atomic (once per block)
    #pragma unroll
    for (int o = 16; o; o >>= 1) acc += __shfl_down_sync(0xffffffffu, acc, o);
    __shared__ float wsum[8];
    if ((threadIdx.x & 31) == 0) wsum[threadIdx.x >> 5] = acc;
    __syncthreads();
    if (threadIdx.x == 0) {
        float ssum = 0.0f;
        #pragma unroll
        for (int w = 0; w < 8; w++) ssum += wsum[w];
        atomicAdd(&g_acc, (double)ssum);
        __threadfence();
        int ticket = atomicAdd(&g_done, 1);
        if (ticket == NMAIN - 1) {             // last block finalizes
            double total = atomicAdd(&g_acc, 0.0);
            double mean  = total / (double)(NSLICE * HW);
            out[0] = (float)log(mean + 1.0);
        }
    }
}

extern "C" void kernel_launch(void* const* d_in, const int* in_sizes, int n_in,
                              void* d_out, int out_size) {
    const float2* S = (const float2*)d_in[0];   // preds_S (8,4,256,256)
    const float2* T = (const float2*)d_in[1];   // preds_T (8,4,256,256)
    (void)in_sizes; (void)n_in; (void)out_size; // target (d_in[2]) unused by reference

    k_prep<<<NPIX / 2 / 256, 256>>>(S, T);
    k_trans<<<384, 256>>>();
    k_main<<<NMAIN, 256>>>((float*)d_out);
}

// round 10
// speedup vs baseline: 1.8418x; 1.0201x over previous
#include <cuda_runtime.h>
#include <cuda_fp16.h>
#include <math.h>

#define HH 256
#define WW 256
#define HW 65536
#define NB 8
#define NSLICE 24      // NB * 3 kept channels
#define NPIX (NB*HW)   // 524288
#define CAP 512        // INF = H + W in reference
#define BIG (1<<20)
#define RPB 4          // rows per block in k_main
#define NMAIN (NSLICE * (HH / RPB))   // 1536 blocks

// -------- device scratch (no allocations allowed) --------
// row-packed mask bits: [plane(2)][slice(24)][row(256)][word(8)] (bit = col within word)
__device__ unsigned g_row[2 * NSLICE * HH * 8];
// column-packed bits: [plane(2)][slice(24)][roww(8)][col(256)] (bit i = row roww*32+i)
__device__ unsigned g_bits[2 * NSLICE * 8 * WW];
__device__ __half2  g_err2[NSLICE * HW / 2];     // (p - t)^2 per kept channel, fp16
__device__ int      g_cnt[2 * NSLICE];           // [0..23] p-counts, [24..47] t-counts
__device__ double   g_acc;
__device__ int      g_done;

// 16-bit -> even bit positions of 32-bit
__device__ __forceinline__ unsigned morton16(unsigned v) {
    v = (v | (v << 8)) & 0x00FF00FFu;
    v = (v | (v << 4)) & 0x0F0F0F0Fu;
    v = (v | (v << 2)) & 0x33333333u;
    v = (v | (v << 1)) & 0x55555555u;
    return v;
}

// per-pixel softmax(4) + argmax(4) -> squared errors of ch 1..3 + 6 mask bits
__device__ __forceinline__ void pixel_work(float s0, float s1, float s2, float s3,
                                           float t0, float t1, float t2, float t3,
                                           float& e1o, float& e2o, float& e3o,
                                           unsigned& mk) {
    float m  = fmaxf(fmaxf(s0, s1), fmaxf(s2, s3));
    float e0 = __expf(s0 - m), e1 = __expf(s1 - m), e2 = __expf(s2 - m), e3 = __expf(s3 - m);
    float inv = 1.0f / (e0 + e1 + e2 + e3);
    float p1 = e1 * inv, p2 = e2 * inv, p3 = e3 * inv;

    int lab = 0; float best = t0;            // first-index-wins (matches jnp.argmax)
    if (t1 > best) { best = t1; lab = 1; }
    if (t2 > best) { best = t2; lab = 2; }
    if (t3 > best) { best = t3; lab = 3; }

    float g1 = (lab == 1) ? 1.0f : 0.0f;
    float g2 = (lab == 2) ? 1.0f : 0.0f;
    float g3 = (lab == 3) ? 1.0f : 0.0f;
    e1o = (p1 - g1) * (p1 - g1);
    e2o = (p2 - g2) * (p2 - g2);
    e3o = (p3 - g3) * (p3 - g3);

    mk = 0;
    if (p1 > 0.5f) mk |= 1u;
    if (p2 > 0.5f) mk |= 2u;
    if (p3 > 0.5f) mk |= 4u;
    mk |= ((unsigned)g1 << 3) | ((unsigned)g2 << 4) | ((unsigned)g3 << 5);
}

// -------- kernel 1: softmax + argmax + err + ballot row-packing (no syncs) --------
// 2 px/thread (float2). One warp = 64 consecutive columns of one row.
__global__ void __launch_bounds__(256) k_prep(const float2* __restrict__ S2,
                                              const float2* __restrict__ T2) {
    if (blockIdx.x == 0) {                      // accumulators consumed only by LATER kernels
        if (threadIdx.x < 2 * NSLICE) g_cnt[threadIdx.x] = 0;
        if (threadIdx.x == 2 * NSLICE) { g_acc = 0.0; g_done = 0; }
    }

    int q    = blockIdx.x * 256 + threadIdx.x; // pixel-pair index
    int b    = q >> 15;                        // 32768 pairs per image (block never straddles b)
    int pq   = q & 32767;
    int lane = threadIdx.x & 31;

    const float2* s = S2 + (size_t)b * 4 * 32768 + pq;
    float2 s0 = s[0], s1 = s[32768], s2 = s[2 * 32768], s3 = s[3 * 32768];
    const float2* t = T2 + (size_t)b * 4 * 32768 + pq;
    float2 t0 = t[0], t1 = t[32768], t2 = t[2 * 32768], t3 = t[3 * 32768];

    float a1, a2, a3, b1, b2, b3;
    unsigned m0, m1;
    pixel_work(s0.x, s1.x, s2.x, s3.x, t0.x, t1.x, t2.x, t3.x, a1, a2, a3, m0);
    pixel_work(s0.y, s1.y, s2.y, s3.y, t0.y, t1.y, t2.y, t3.y, b1, b2, b3, m1);

    int base = (b * 3) * 32768 + pq;
    g_err2[base]             = __floats2half2_rn(a1, b1);
    g_err2[base + 32768]     = __floats2half2_rn(a2, b2);
    g_err2[base + 2 * 32768] = __floats2half2_rn(a3, b3);

    // ballots per bit-plane (px0 and px1 separately)
    unsigned B00 = __ballot_sync(0xffffffffu, (m0 >> 0) & 1), B01 = __ballot_sync(0xffffffffu, (m1 >> 0) & 1);
    unsigned B10 = __ballot_sync(0xffffffffu, (m0 >> 1) & 1), B11 = __ballot_sync(0xffffffffu, (m1 >> 1) & 1);
    unsigned B20 = __ballot_sync(0xffffffffu, (m0 >> 2) & 1), B21 = __ballot_sync(0xffffffffu, (m1 >> 2) & 1);
    unsigned B30 = __ballot_sync(0xffffffffu, (m0 >> 3) & 1), B31 = __ballot_sync(0xffffffffu, (m1 >> 3) & 1);
    unsigned B40 = __ballot_sync(0xffffffffu, (m0 >> 4) & 1), B41 = __ballot_sync(0xffffffffu, (m1 >> 4) & 1);
    unsigned B50 = __ballot_sync(0xffffffffu, (m0 >> 5) & 1), B51 = __ballot_sync(0xffffffffu, (m1 >> 5) & 1);

    // lanes 0..11 each store one packed word: plane = lane>>1, hi-half = lane&1
    int beta = lane >> 1;
    int hi   = lane & 1;
    unsigned sel0 = (beta == 0) ? B00 : (beta == 1) ? B10 : (beta == 2) ? B20
                  : (beta == 3) ? B30 : (beta == 4) ? B40 : B50;
    unsigned sel1 = (beta == 0) ? B01 : (beta == 1) ? B11 : (beta == 2) ? B21
                  : (beta == 3) ? B31 : (beta == 4) ? B41 : B51;
    unsigned p0 = hi ? (sel0 >> 16) : (sel0 & 0xFFFFu);
    unsigned p1 = hi ? (sel1 >> 16) : (sel1 & 0xFFFFu);
    unsigned word = morton16(p0) | (morton16(p1) << 1);

    if (lane < 12) {
        int row   = pq >> 7;                     // 128 pairs per row
        int wbase = (((pq & 127) >> 5) << 1);    // warp covers words wbase, wbase+1
        int P  = (beta >= 3) ? 1 : 0;
        int cc = beta - 3 * P;
        int sl = b * 3 + cc;
        g_row[((P * NSLICE + sl) * HH + row) * 8 + wbase + hi] = word;
    }
}

// -------- kernel 2: 32x32 bit-matrix transpose + per-slice counts --------
// one warp per tile; tiles = 2 planes * 24 slices * 8 row-words * 8 col-words = 3072
__global__ void __launch_bounds__(256) k_trans() {
    int warpid = (blockIdx.x * 256 + threadIdx.x) >> 5;   // 0..3071
    int lane   = threadIdx.x & 31;
    int C  = warpid & 7;          // column-word of source (32 columns)
    int W  = (warpid >> 3) & 7;   // row-word of dest (32 rows)
    int ps = warpid >> 6;         // plane*NSLICE + slice, 0..47

    unsigned in = g_row[((size_t)ps * HH + 32 * W + lane) * 8 + C];

    // counts (valid = any && !all): one atomic per warp
    int c = __reduce_add_sync(0xffffffffu, __popc(in));
    if (lane == 0) atomicAdd(&g_cnt[ps], c);

    unsigned out = 0;
    #pragma unroll
    for (int k = 0; k < 32; k++) {
        unsigned bal = __ballot_sync(0xffffffffu, (in >> k) & 1u);
        if (lane == k) out = bal;
    }
    g_bits[(size_t)ps * 8 * WW + W * WW + 32 * C + lane] = out;
}

// adaptive exact search. Facts: G >= 0 everywhere, best = G[j] >= 1 (selected
// array never contains the own pixel). If best <= 1 no candidate G[k]+d^2 can
// beat it (d^2 >= 1). Unconditional d=1 probe (clamped = over-estimate, safe),
// then rare dependent tail from d=2 (only if best > 4).
__device__ __forceinline__ int edt_search(const int* __restrict__ G, int j) {
    int best = G[j];
    if (best <= 1) return best;
    int a = G[max(j - 1, 0)] + 1;
    int b = G[min(j + 1, WW - 1)] + 1;
    best = min(best, min(a, b));
    if (best > 4) {
        for (int d = 2; d < WW; d++) {
            int dd = d * d;
            if (dd >= best) break;
            int jm = j - d, jp = j + d;
            if (jm >= 0) best = min(best, G[jm] + dd);
            if (jp < WW) best = min(best, G[jp] + dd);
        }
    }
    return best;
}

// on-demand out-of-word fallbacks for one plane/column (early-break; usually 1 iter)
__device__ __forceinline__ void fallbacks(const unsigned* __restrict__ P, int j, int w0,
                                          int& fb0, int& fb1, int& la0, int& la1) {
    fb0 = BIG; fb1 = BIG;
    for (int w = w0 + 1; w < 8 && (fb0 == BIG || fb1 == BIG); w++) {
        unsigned ww = P[w * WW + j];
        if (fb0 == BIG && ~ww) fb0 = w * 32 + __ffs(~ww) - 1;
        if (fb1 == BIG &&  ww) fb1 = w * 32 + __ffs(ww) - 1;
    }
    la0 = -BIG; la1 = -BIG;
    for (int w = w0 - 1; w >= 0 && (la0 == -BIG || la1 == -BIG); w--) {
        unsigned ww = P[w * WW + j];
        if (la0 == -BIG && ~ww) la0 = w * 32 + 31 - __clz(~ww);
        if (la1 == -BIG &&  ww) la1 = w * 32 + 31 - __clz(ww);
    }
}

// per-row vertical distances from register word + precomputed fallbacks
__device__ __forceinline__ void vrow(unsigned cur, int br, int R,
                                     int fb0, int fb1, int la0, int la1,
                                     int& d0, int& d1) {
    unsigned hi = 0xFFFFFFFFu << br;
    unsigned lo = 0xFFFFFFFFu >> (31 - br);
    unsigned nc = ~cur;

    unsigned x0 = nc & hi;
    int dn0 = x0 ? (__ffs(x0) - 1 - br) : (fb0 - R);
    unsigned y0 = nc & lo;
    int up0 = y0 ? (br - (31 - __clz(y0))) : (R - la0);
    d0 = min(min(dn0, up0), CAP);

    unsigned x1 = cur & hi;
    int dn1 = x1 ? (__ffs(x1) - 1 - br) : (fb1 - R);
    unsigned y1 = cur & lo;
    int up1 = y1 ? (br - (31 - __clz(y1))) : (R - la1);
    d1 = min(min(dn1, up1), CAP);
}

// -------- kernel 3: fused vertical+horizontal EDT + loss + finalize --------
// block = (slice, 4-row band); grid = 24*64 = 1536
__global__ void __launch_bounds__(256) k_main(float* __restrict__ out) {
    int s    = blockIdx.x >> 6;    // slice 0..23
    int band = blockIdx.x & 63;    // 4-row band 0..63
    int j    = threadIdx.x;        // column
    int w0   = band >> 3;          // word holding all 4 rows
    int bb   = (band & 7) * 4;     // bit base within word

    const unsigned* Pp = g_bits + (size_t)(0 * NSLICE + s) * 8 * WW;
    const unsigned* Pt = g_bits + (size_t)(1 * NSLICE + s) * 8 * WW;

    unsigned curp = Pp[w0 * WW + j];
    unsigned curt = Pt[w0 * WW + j];
    int fb0p, fb1p, la0p, la1p, fb0t, fb1t, la0t, la1t;
    fallbacks(Pp, j, w0, fb0p, fb1p, la0p, la1p);
    fallbacks(Pt, j, w0, fb0t, fb1t, la0t, la1t);

    __shared__ int G[RPB][4][WW];
    #pragma unroll
    for (int r = 0; r < RPB; r++) {
        int br = bb + r;
        int R  = band * RPB + r;
        int d0, d1;
        vrow(curp, br, R, fb0p, fb1p, la0p, la1p, d0, d1);
        G[r][0][j] = d0 * d0;
        G[r][1][j] = d1 * d1;
        vrow(curt, br, R, fb0t, fb1t, la0t, la1t, d0, d1);
        G[r][2][j] = d0 * d0;
        G[r][3][j] = d1 * d1;
    }
    __syncthreads();               // ONE barrier per block

    int cp = g_cnt[s], ct = g_cnt[NSLICE + s];
    float vp = (cp > 0 && cp < HW) ? 1.0f : 0.0f;
    float vt = (ct > 0 && ct < HW) ? 1.0f : 0.0f;

    const __half* erow = ((const __half*)g_err2) + (size_t)s * HW + (size_t)band * RPB * WW + j;

    float acc = 0.0f;
    #pragma unroll
    for (int r = 0; r < RPB; r++) {
        int br = bb + r;
        int p_true = (curp >> br) & 1;
        int t_true = (curt >> br) & 1;
        int dp = edt_search(&G[r][p_true ? 0 : 1][0], j);
        int dt = edt_search(&G[r][t_true ? 2 : 3][0], j);
        float err = __half2float(erow[r * WW]);
        acc += err * ((float)dp * vp + (float)dt * vt);
    }

    // block reduction -> double atomic (once per block)
    #pragma unroll
    for (int o = 16; o; o >>= 1) acc += __shfl_down_sync(0xffffffffu, acc, o);
    __shared__ float wsum[8];
    if ((threadIdx.x & 31) == 0) wsum[threadIdx.x >> 5] = acc;
    __syncthreads();
    if (threadIdx.x == 0) {
        float ssum = 0.0f;
        #pragma unroll
        for (int w = 0; w < 8; w++) ssum += wsum[w];
        atomicAdd(&g_acc, (double)ssum);
        __threadfence();
        int ticket = atomicAdd(&g_done, 1);
        if (ticket == NMAIN - 1) {             // last block finalizes
            double total = atomicAdd(&g_acc, 0.0);
            double mean  = total / (double)(NSLICE * HW);
            out[0] = (float)log(mean + 1.0);
        }
    }
}

extern "C" void kernel_launch(void* const* d_in, const int* in_sizes, int n_in,
                              void* d_out, int out_size) {
    const float2* S = (const float2*)d_in[0];   // preds_S (8,4,256,256)
    const float2* T = (const float2*)d_in[1];   // preds_T (8,4,256,256)
    (void)in_sizes; (void)n_in; (void)out_size; // target (d_in[2]) unused by reference

    k_prep<<<NPIX / 2 / 256, 256>>>(S, T);
    k_trans<<<384, 256>>>();
    k_main<<<NMAIN, 256>>>((float*)d_out);
}